// round 15
// baseline (speedup 1.0000x reference)
#include <cuda_runtime.h>
#include <cuda_bf16.h>
#include <cstdint>
#include <cstddef>

constexpr int Bn = 8;
constexpr int Tn = 2304;
constexpr int NROW = Bn * Tn;          // 18432
constexpr float LAMBDA_INIT_F = 0.6192834728526787f;
constexpr float QSCALE = 0.18033688011112042f;   // (1/8) * log2(e)

typedef unsigned long long ull;

__device__ float g_lam;
__device__ __align__(16) __nv_bfloat16 g_xh[NROW * 1024];
__device__ __align__(16) __nv_bfloat16 g_xl[NROW * 1024];
__device__ __align__(16) __nv_bfloat16 g_wh[9 * 128 * 1024];
__device__ __align__(16) __nv_bfloat16 g_wl[9 * 128 * 1024];
__device__ __align__(16) __nv_bfloat16 g_qh[NROW * 128];
__device__ __align__(16) __nv_bfloat16 g_ql[NROW * 128];
__device__ __align__(16) __nv_bfloat16 g_kh[NROW * 128];
__device__ __align__(16) __nv_bfloat16 g_kl[NROW * 128];
__device__ __align__(16) __nv_bfloat16 g_vh[NROW * 128];
__device__ __align__(16) __nv_bfloat16 g_vl[NROW * 128];

__device__ __forceinline__ float fast_exp2(float x) {
  x = fmaxf(x, -125.0f);
  float t = x + 12582912.0f;
  int e = __float_as_int(t) - 0x4B400000;
  float f = x - (t - 12582912.0f);
  float p =        1.3333558e-3f;
  p = fmaf(p, f,   9.6181291e-3f);
  p = fmaf(p, f,   5.5504109e-2f);
  p = fmaf(p, f,   2.4022651e-1f);
  p = fmaf(p, f,   6.9314718e-1f);
  p = fmaf(p, f,   1.0f);
  return __int_as_float(__float_as_int(p) + (e << 23));
}

__device__ __forceinline__ uint32_t smem_u32(const void* p) {
  uint32_t a;
  asm("{ .reg .u64 t; cvta.to.shared.u64 t, %1; cvt.u32.u64 %0, t; }" : "=r"(a) : "l"(p));
  return a;
}
__device__ __forceinline__ uint32_t sw128(uint32_t off) {
  return off ^ ((off >> 3) & 0x70);
}
__device__ __forceinline__ void cpasync16(uint32_t dst, const void* src) {
  asm volatile("cp.async.cg.shared.global [%0], [%1], 16;" :: "r"(dst), "l"(src));
}
__device__ __forceinline__ void cp_commit() {
  asm volatile("cp.async.commit_group;" ::: "memory");
}
__device__ __forceinline__ void cp_wait1() {
  asm volatile("cp.async.wait_group 1;" ::: "memory");
}
__device__ __forceinline__ void cp_wait0() {
  asm volatile("cp.async.wait_group 0;" ::: "memory");
}
__device__ __forceinline__ void ldsm4(uint32_t* r, uint32_t a) {
  asm volatile("ldmatrix.sync.aligned.m8n8.x4.shared.b16 {%0,%1,%2,%3}, [%4];"
               : "=r"(r[0]), "=r"(r[1]), "=r"(r[2]), "=r"(r[3]) : "r"(a));
}
__device__ __forceinline__ void ldsm4t(uint32_t* r, uint32_t a) {
  asm volatile("ldmatrix.sync.aligned.m8n8.x4.trans.shared.b16 {%0,%1,%2,%3}, [%4];"
               : "=r"(r[0]), "=r"(r[1]), "=r"(r[2]), "=r"(r[3]) : "r"(a));
}
__device__ __forceinline__ void mma16816(float* d, const uint32_t* a, uint32_t b0, uint32_t b1) {
  asm volatile(
      "mma.sync.aligned.m16n8k16.row.col.f32.bf16.bf16.f32 "
      "{%0,%1,%2,%3},{%4,%5,%6,%7},{%8,%9},{%0,%1,%2,%3};"
      : "+f"(d[0]), "+f"(d[1]), "+f"(d[2]), "+f"(d[3])
      : "r"(a[0]), "r"(a[1]), "r"(a[2]), "r"(a[3]), "r"(b0), "r"(b1));
}
__device__ __forceinline__ void hilo(float a, float b, uint32_t& h, uint32_t& l) {
  __nv_bfloat16 ha = __float2bfloat16_rn(a), hb = __float2bfloat16_rn(b);
  __nv_bfloat162 H; H.x = ha; H.y = hb;
  h = *(uint32_t*)&H;
  __nv_bfloat162 L;
  L.x = __float2bfloat16_rn(a - __bfloat162float(ha));
  L.y = __float2bfloat16_rn(b - __bfloat162float(hb));
  l = *(uint32_t*)&L;
}

// ---------------- LN + bf16 hi/lo split of x ----------------
struct NormParams {
  const float* x;
  const float* g[3];
  const float* b[3];
};

__global__ void norm_split_kernel(NormParams p) {
  int row = blockIdx.x * 8 + threadIdx.y;
  int t = row % Tn;
  int seg = t < 128 ? 0 : (t < 2176 ? 1 : 2);
  const float* __restrict__ gg = p.g[seg];
  const float* __restrict__ bb = p.b[seg];
  int lid = threadIdx.x;
  const float* xr = p.x + (size_t)row * 1024;

  float v[32];
  float s = 0.f, ss = 0.f;
#pragma unroll
  for (int i = 0; i < 8; i++) {
    float4 f = *(const float4*)&xr[i * 128 + lid * 4];
    v[i * 4 + 0] = f.x; v[i * 4 + 1] = f.y; v[i * 4 + 2] = f.z; v[i * 4 + 3] = f.w;
    s += f.x + f.y + f.z + f.w;
    ss += f.x * f.x + f.y * f.y + f.z * f.z + f.w * f.w;
  }
#pragma unroll
  for (int o = 16; o > 0; o >>= 1) {
    s += __shfl_xor_sync(0xffffffffu, s, o);
    ss += __shfl_xor_sync(0xffffffffu, ss, o);
  }
  float mean = s * (1.0f / 1024.0f);
  float var = fmaf(-mean, mean, ss * (1.0f / 1024.0f));
  float rstd = rsqrtf(var + 1e-5f);

  __nv_bfloat16* xh = g_xh + (size_t)row * 1024;
  __nv_bfloat16* xl = g_xl + (size_t)row * 1024;
#pragma unroll
  for (int i = 0; i < 8; i++) {
    int k = i * 128 + lid * 4;
    float4 gf = *(const float4*)&gg[k];
    float4 bf = *(const float4*)&bb[k];
    float a0 = (v[i * 4 + 0] - mean) * rstd * gf.x + bf.x;
    float a1 = (v[i * 4 + 1] - mean) * rstd * gf.y + bf.y;
    float a2 = (v[i * 4 + 2] - mean) * rstd * gf.z + bf.z;
    float a3 = (v[i * 4 + 3] - mean) * rstd * gf.w + bf.w;
    uint2 hp, lp;
    hilo(a0, a1, hp.x, lp.x);
    hilo(a2, a3, hp.y, lp.y);
    *(uint2*)&xh[k] = hp;
    *(uint2*)&xl[k] = lp;
  }
}

// ---------------- weight transpose + bf16 hi/lo split (+ fused lambda) ----------------
struct WPrepParams {
  const float* W[9];
  const float* lq1;
  const float* lq2;
  const float* lk1;
  const float* lk2;
};

__global__ void wprep_kernel(WPrepParams p) {
  __shared__ float tile[32][33];
  int mat = blockIdx.z;
  const float* __restrict__ W = p.W[mat];
  int kb = blockIdx.x * 32, nb = blockIdx.y * 32;
  int tx = threadIdx.x, ty = threadIdx.y;
  tile[ty][tx] = W[(size_t)(kb + ty) * 128 + nb + tx];
  __syncthreads();
  float v = tile[tx][ty];
  __nv_bfloat16 h = __float2bfloat16_rn(v);
  __nv_bfloat16 l = __float2bfloat16_rn(v - __bfloat162float(h));
  size_t o = (size_t)mat * 128 * 1024 + (size_t)(nb + ty) * 1024 + kb + tx;
  g_wh[o] = h;
  g_wl[o] = l;

  // fused lambda (one warp of one block)
  if (mat == 0 && blockIdx.x == 0 && blockIdx.y == 0 && ty == 0) {
    float a = p.lq1[tx] * p.lk1[tx] + p.lq1[tx + 32] * p.lk1[tx + 32];
    float c = p.lq2[tx] * p.lk2[tx] + p.lq2[tx + 32] * p.lk2[tx + 32];
#pragma unroll
    for (int off = 16; off > 0; off >>= 1) {
      a += __shfl_xor_sync(0xffffffffu, a, off);
      c += __shfl_xor_sync(0xffffffffu, c, off);
    }
    if (tx == 0) g_lam = expf(a) - expf(c) + LAMBDA_INIT_F;
  }
}

// ---------------- projection GEMM (unchanged R10) ----------------
constexpr int PB_AH = 0;
constexpr int PB_AL = 16384;
constexpr int PB_BH = 32768;
constexpr int PB_BL = 40960;
constexpr int PBUF = 49152;
constexpr int PROJ_SMEM = 2 * PBUF;   // 98304

__global__ __launch_bounds__(256, 2) void proj_mma_kernel() {
  extern __shared__ char smem[];
  uint32_t sb = smem_u32(smem);
  const int tid = threadIdx.x;
  const int rt = blockIdx.x, mat = blockIdx.y, nh = blockIdx.z;
  const int row0 = rt * 128;
  const int t0 = row0 % Tn;
  const int seg = t0 < 128 ? 0 : (t0 < 2176 ? 1 : 2);
  const size_t wbase = (size_t)(mat * 3 + seg) * 128 * 1024 + (size_t)nh * 64 * 1024;
  const __nv_bfloat16* __restrict__ Ah_g = g_xh + (size_t)row0 * 1024;
  const __nv_bfloat16* __restrict__ Al_g = g_xl + (size_t)row0 * 1024;
  const __nv_bfloat16* __restrict__ Bh_g = g_wh + wbase;
  const __nv_bfloat16* __restrict__ Bl_g = g_wl + wbase;

  const int lane = tid & 31;
  const int wid = tid >> 5;
  const int wm = (wid & 3) * 32;
  const int wn = (wid >> 2) * 32;
  const int lrow = lane & 7;
  const int sel = lane >> 3;
  const int selm = (sel & 1) * 8;
  const int selc = (sel >> 1) * 16;

  float acc[2][4][4];
#pragma unroll
  for (int mt = 0; mt < 2; mt++)
#pragma unroll
    for (int nt = 0; nt < 4; nt++)
#pragma unroll
      for (int j = 0; j < 4; j++) acc[mt][nt][j] = 0.f;

  auto issue = [&](int ch, int b) {
    const int k0 = ch * 64;
    const uint32_t dst = sb + b * PBUF;
#pragma unroll
    for (int it = 0; it < 4; it++) {
      int i = tid + it * 256;
      int r = i >> 3, c = i & 7;
      uint32_t d = sw128((uint32_t)(r * 128 + c * 16));
      size_t go = (size_t)r * 1024 + k0 + c * 8;
      cpasync16(dst + PB_AH + d, Ah_g + go);
      cpasync16(dst + PB_AL + d, Al_g + go);
    }
#pragma unroll
    for (int it = 0; it < 2; it++) {
      int i = tid + it * 256;
      int r = i >> 3, c = i & 7;
      uint32_t d = sw128((uint32_t)(r * 128 + c * 16));
      size_t go = (size_t)r * 1024 + k0 + c * 8;
      cpasync16(dst + PB_BH + d, Bh_g + go);
      cpasync16(dst + PB_BL + d, Bl_g + go);
    }
  };

  issue(0, 0);
  cp_commit();

  for (int ch = 0; ch < 16; ch++) {
    if (ch + 1 < 16) {
      issue(ch + 1, (ch + 1) & 1);
      cp_commit();
      cp_wait1();
    } else {
      cp_wait0();
    }
    __syncthreads();

    const uint32_t base = sb + (ch & 1) * PBUF;
#pragma unroll
    for (int ks = 0; ks < 4; ks++) {
      const int colb = ks * 32 + selc;
      uint32_t ah[2][4], al[2][4];
#pragma unroll
      for (int mt = 0; mt < 2; mt++) {
        int r = wm + mt * 16 + selm + lrow;
        uint32_t off = sw128((uint32_t)(r * 128 + colb));
        ldsm4(ah[mt], base + PB_AH + off);
        ldsm4(al[mt], base + PB_AL + off);
      }
      uint32_t bh[4][2], bl[4][2];
#pragma unroll
      for (int np = 0; np < 2; np++) {
        int r = wn + np * 16 + selm + lrow;
        uint32_t off = sw128((uint32_t)(r * 128 + colb));
        uint32_t t4[4];
        ldsm4(t4, base + PB_BH + off);
        bh[2 * np][0] = t4[0]; bh[2 * np][1] = t4[2];
        bh[2 * np + 1][0] = t4[1]; bh[2 * np + 1][1] = t4[3];
        ldsm4(t4, base + PB_BL + off);
        bl[2 * np][0] = t4[0]; bl[2 * np][1] = t4[2];
        bl[2 * np + 1][0] = t4[1]; bl[2 * np + 1][1] = t4[3];
      }
#pragma unroll
      for (int mt = 0; mt < 2; mt++)
#pragma unroll
        for (int nt = 0; nt < 4; nt++) {
          mma16816(acc[mt][nt], ah[mt], bh[nt][0], bh[nt][1]);
          mma16816(acc[mt][nt], ah[mt], bl[nt][0], bl[nt][1]);
          mma16816(acc[mt][nt], al[mt], bh[nt][0], bh[nt][1]);
        }
    }
    __syncthreads();
  }

  __nv_bfloat16* __restrict__ oh = (mat == 0) ? g_qh : (mat == 1) ? g_kh : g_vh;
  __nv_bfloat16* __restrict__ ol = (mat == 0) ? g_ql : (mat == 1) ? g_kl : g_vl;
  const int orow = lane >> 2, ocol = (lane & 3) * 2;
#pragma unroll
  for (int mt = 0; mt < 2; mt++)
#pragma unroll
    for (int nt = 0; nt < 4; nt++) {
      int r = row0 + wm + mt * 16 + orow;
      int c = nh * 64 + wn + nt * 8 + ocol;
      uint32_t h0, l0, h1, l1;
      hilo(acc[mt][nt][0], acc[mt][nt][1], h0, l0);
      hilo(acc[mt][nt][2], acc[mt][nt][3], h1, l1);
      *(uint32_t*)&oh[(size_t)r * 128 + c] = h0;
      *(uint32_t*)&ol[(size_t)r * 128 + c] = l0;
      *(uint32_t*)&oh[(size_t)(r + 8) * 128 + c] = h1;
      *(uint32_t*)&ol[(size_t)(r + 8) * 128 + c] = l1;
    }
}

// ---------------- tensor-core dual flash attention ----------------
// map-split warps (R13) + reg-Q + single barrier per tile.
constexpr int KVBUF = 65536;              // Kh(2x8K) Kl(2x8K) Vh(2x8K) Vl(2x8K)
constexpr int AOFF_Q   = 131072;          // Qh d0-63, Qh d64-127, Ql d0-63, Ql d64-127
constexpr int AOFF_SCR = 163840;          // 64 x 132 f32 = 33792 B
constexpr int ATTN_SMEM = 197632;

__global__ __launch_bounds__(256, 1) void attn_mma_kernel(
    const float* __restrict__ gam, const float* __restrict__ bet,
    float* __restrict__ out) {
  extern __shared__ char smem[];
  uint32_t sb = smem_u32(smem);
  float* SCR = (float*)(smem + AOFF_SCR);

  const int tid = threadIdx.x;
  const int lane = tid & 31;
  const int wid = tid >> 5;
  const int wm = (wid & 3) * 16;
  const int m = wid >> 2;       // map 0/1
  const int lrow = lane & 7;
  const int sel = lane >> 3;
  const int selm = (sel & 1) * 8;
  const int selc = (sel >> 1) * 16;
  const int r = lane >> 2;
  const int cq = (lane & 3) * 2;

  const int rowbase = (int)blockIdx.y * Tn;
  const float lam = g_lam;

  auto issueKV = [&](int kt, int b) {
    const int k0g = kt * 64;
    const uint32_t dst = sb + b * KVBUF;
#pragma unroll
    for (int it = 0; it < 16; it++) {
      int idx = tid + it * 256;
      int part = idx >> 9;
      int j = idx & 511;
      int key = j >> 3, c = j & 7;
      uint32_t so = (uint32_t)part * 8192 + sw128((uint32_t)(key * 128 + c * 16));
      size_t go = (size_t)(rowbase + k0g + key) * 128 + (part & 1) * 64 + c * 8;
      const __nv_bfloat16* src =
          (part < 2) ? g_kh : (part < 4) ? g_kl : (part < 6) ? g_vh : g_vl;
      cpasync16(dst + so, src + go);
    }
  };
  auto issueQ = [&](int q0) {
#pragma unroll
    for (int it = 0; it < 8; it++) {
      int idx = tid + it * 256;
      int part = idx >> 9;
      int j = idx & 511;
      int row = j >> 3, c = j & 7;
      uint32_t so = AOFF_Q + (uint32_t)part * 8192 + sw128((uint32_t)(row * 128 + c * 16));
      size_t go = (size_t)(rowbase + q0 + row) * 128 + (part & 1) * 64 + c * 8;
      const __nv_bfloat16* src = (part < 2) ? g_qh : g_ql;
      cpasync16(sb + so, src + go);
    }
  };

  for (int half = 0; half < 2; half++) {
    const int qt = half ? (35 - (int)blockIdx.x) : (int)blockIdx.x;
    const int q0 = qt * 64;

    float oacc[16][4];
    float mrow[2], lrow_s[2];
#pragma unroll
    for (int h = 0; h < 2; h++) { mrow[h] = -3.0e38f; lrow_s[h] = 0.f; }
#pragma unroll
    for (int nt = 0; nt < 16; nt++)
#pragma unroll
      for (int j = 0; j < 4; j++) oacc[nt][j] = 0.f;

    // prologue: Q + KV0 (group 0); wait; Q frags to regs; then issue KV1.
    issueQ(q0);
    issueKV(0, 0);
    cp_commit();
    cp_wait0();
    __syncthreads();

    uint32_t qfh[4][4], qfl[4][4];
    {
      const uint32_t Qh = sb + AOFF_Q + m * 8192;
      const uint32_t Ql = sb + AOFF_Q + 16384 + m * 8192;
#pragma unroll
      for (int ks = 0; ks < 4; ks++) {
        uint32_t aoff = sw128((uint32_t)((wm + selm + lrow) * 128 + ks * 32 + selc));
        ldsm4(qfh[ks], Qh + aoff);
        ldsm4(qfl[ks], Ql + aoff);
      }
    }
    if (qt >= 1) {
      issueKV(1, 1);
      cp_commit();
    }

    for (int kt = 0; kt <= qt; kt++) {
      if (kt > 0) {
        cp_wait0();
        __syncthreads();   // KV(kt) visible; all warps done reading buffer kt-1
        if (kt + 1 <= qt) {
          issueKV(kt + 1, (kt + 1) & 1);   // overwrites buffer (kt-1)&1 — safe
          cp_commit();
        }
      }

      const uint32_t buf = sb + (kt & 1) * KVBUF;
      const int k0 = kt * 64;

      // ---- S = Q K^T (16 rows x 64 keys, this map) ----
      float sacc[8][4];
#pragma unroll
      for (int nt = 0; nt < 8; nt++)
#pragma unroll
        for (int j = 0; j < 4; j++) sacc[nt][j] = 0.f;

      {
        const uint32_t Kh = buf + m * 8192;
        const uint32_t Kl = buf + 16384 + m * 8192;
#pragma unroll
        for (int ks = 0; ks < 4; ks++) {
          const int colb = ks * 32 + selc;
          uint32_t bh[8][2], bl[8][2];
#pragma unroll
          for (int np = 0; np < 4; np++) {
            uint32_t boff = sw128((uint32_t)((np * 16 + selm + lrow) * 128 + colb));
            uint32_t t4[4];
            ldsm4(t4, Kh + boff);
            bh[2 * np][0] = t4[0]; bh[2 * np][1] = t4[2];
            bh[2 * np + 1][0] = t4[1]; bh[2 * np + 1][1] = t4[3];
            ldsm4(t4, Kl + boff);
            bl[2 * np][0] = t4[0]; bl[2 * np][1] = t4[2];
            bl[2 * np + 1][0] = t4[1]; bl[2 * np + 1][1] = t4[3];
          }
#pragma unroll
          for (int nt = 0; nt < 8; nt++) {
            mma16816(sacc[nt], qfh[ks], bh[nt][0], bh[nt][1]);
            mma16816(sacc[nt], qfl[ks], bh[nt][0], bh[nt][1]);
            mma16816(sacc[nt], qfh[ks], bl[nt][0], bl[nt][1]);
          }
        }
      }

      // ---- warp-local softmax ----
      const bool diag = (kt == qt);
      float mx[2] = {-3.0e38f, -3.0e38f};
#pragma unroll
      for (int nt = 0; nt < 8; nt++)
#pragma unroll
        for (int h = 0; h < 2; h++)
#pragma unroll
          for (int j = 0; j < 2; j++) {
            float v = sacc[nt][h * 2 + j] * QSCALE;
            if (diag && (k0 + nt * 8 + cq + j) > (q0 + wm + r + h * 8)) v = -3.0e38f;
            sacc[nt][h * 2 + j] = v;
            mx[h] = fmaxf(mx[h], v);
          }
#pragma unroll
      for (int h = 0; h < 2; h++) {
        mx[h] = fmaxf(mx[h], __shfl_xor_sync(0xffffffffu, mx[h], 1));
        mx[h] = fmaxf(mx[h], __shfl_xor_sync(0xffffffffu, mx[h], 2));
      }

      float alpha[2], lsum[2] = {0.f, 0.f};
#pragma unroll
      for (int h = 0; h < 2; h++) {
        float mn = fmaxf(mrow[h], mx[h]);
        alpha[h] = fast_exp2(mrow[h] - mn);
        mrow[h] = mn;
      }

      uint32_t pfh[4][4], pfl[4][4];
#pragma unroll
      for (int nt = 0; nt < 8; nt++)
#pragma unroll
        for (int h = 0; h < 2; h++) {
          float p0 = fast_exp2(sacc[nt][h * 2 + 0] - mrow[h]);
          float p1 = fast_exp2(sacc[nt][h * 2 + 1] - mrow[h]);
          lsum[h] += p0 + p1;
          sacc[nt][h * 2 + 0] = p0;
          sacc[nt][h * 2 + 1] = p1;
        }
#pragma unroll
      for (int ks = 0; ks < 4; ks++) {
        hilo(sacc[2 * ks][0], sacc[2 * ks][1], pfh[ks][0], pfl[ks][0]);
        hilo(sacc[2 * ks][2], sacc[2 * ks][3], pfh[ks][1], pfl[ks][1]);
        hilo(sacc[2 * ks + 1][0], sacc[2 * ks + 1][1], pfh[ks][2], pfl[ks][2]);
        hilo(sacc[2 * ks + 1][2], sacc[2 * ks + 1][3], pfh[ks][3], pfl[ks][3]);
      }
#pragma unroll
      for (int h = 0; h < 2; h++) {
        lsum[h] += __shfl_xor_sync(0xffffffffu, lsum[h], 1);
        lsum[h] += __shfl_xor_sync(0xffffffffu, lsum[h], 2);
        lrow_s[h] = lrow_s[h] * alpha[h] + lsum[h];
      }
#pragma unroll
      for (int nt = 0; nt < 16; nt++) {
        oacc[nt][0] *= alpha[0];
        oacc[nt][1] *= alpha[0];
        oacc[nt][2] *= alpha[1];
        oacc[nt][3] *= alpha[1];
      }

      // ---- O += P V ----
#pragma unroll
      for (int ks = 0; ks < 4; ks++) {
        const int vrow = ks * 16 + selm + lrow;
#pragma unroll
        for (int np = 0; np < 8; np++) {
          const int part = np >> 2;
          const uint32_t boff = (uint32_t)part * 8192 +
              sw128((uint32_t)(vrow * 128 + (np & 3) * 32 + selc));
          uint32_t vh4[4], vl4[4];
          ldsm4t(vh4, buf + 32768 + boff);
          ldsm4t(vl4, buf + 49152 + boff);
#pragma unroll
          for (int e = 0; e < 2; e++) {
            float* d = oacc[2 * np + e];
            mma16816(d, pfh[ks], vh4[2 * e], vh4[2 * e + 1]);
            mma16816(d, pfl[ks], vh4[2 * e], vh4[2 * e + 1]);
            mma16816(d, pfh[ks], vl4[2 * e], vl4[2 * e + 1]);
          }
        }
      }
      // no end-of-tile barrier: next tile's top barrier provides the ordering
    }

    // ---- epilogue: cross-map combine + output LN ----
    if (m == 1) {
      float inv2[2];
#pragma unroll
      for (int h = 0; h < 2; h++) inv2[h] = lam / lrow_s[h];
#pragma unroll
      for (int nt = 0; nt < 16; nt++)
#pragma unroll
        for (int h = 0; h < 2; h++) {
          int rr = wm + r + h * 8;
          SCR[rr * 132 + nt * 8 + cq]     = oacc[nt][h * 2 + 0] * inv2[h];
          SCR[rr * 132 + nt * 8 + cq + 1] = oacc[nt][h * 2 + 1] * inv2[h];
        }
    }
    __syncthreads();
    if (m == 0) {
      float inv1[2];
#pragma unroll
      for (int h = 0; h < 2; h++) inv1[h] = 1.0f / lrow_s[h];
      float att[16][4];
      float rs[2] = {0.f, 0.f};
#pragma unroll
      for (int nt = 0; nt < 16; nt++)
#pragma unroll
        for (int h = 0; h < 2; h++) {
          int rr = wm + r + h * 8;
          float a0 = oacc[nt][h * 2 + 0] * inv1[h] - SCR[rr * 132 + nt * 8 + cq];
          float a1 = oacc[nt][h * 2 + 1] * inv1[h] - SCR[rr * 132 + nt * 8 + cq + 1];
          att[nt][h * 2 + 0] = a0;
          att[nt][h * 2 + 1] = a1;
          rs[h] += a0 + a1;
        }
#pragma unroll
      for (int h = 0; h < 2; h++) {
        rs[h] += __shfl_xor_sync(0xffffffffu, rs[h], 1);
        rs[h] += __shfl_xor_sync(0xffffffffu, rs[h], 2);
      }
      float mean_[2];
#pragma unroll
      for (int h = 0; h < 2; h++) mean_[h] = rs[h] * (1.0f / 128.0f);

      float vs[2] = {0.f, 0.f};
#pragma unroll
      for (int nt = 0; nt < 16; nt++)
#pragma unroll
        for (int h = 0; h < 2; h++)
#pragma unroll
          for (int j = 0; j < 2; j++) {
            float a = att[nt][h * 2 + j] - mean_[h];
            vs[h] += a * a;
          }
#pragma unroll
      for (int h = 0; h < 2; h++) {
        vs[h] += __shfl_xor_sync(0xffffffffu, vs[h], 1);
        vs[h] += __shfl_xor_sync(0xffffffffu, vs[h], 2);
      }
      float rstd_[2];
#pragma unroll
      for (int h = 0; h < 2; h++)
        rstd_[h] = rsqrtf(vs[h] * (1.0f / 128.0f) + 1e-5f);

#pragma unroll
      for (int nt = 0; nt < 16; nt++) {
        int c = nt * 8 + cq;
        float2 g2 = *(const float2*)&gam[c];
        float2 b2 = *(const float2*)&bet[c];
#pragma unroll
        for (int h = 0; h < 2; h++) {
          float o0 = (att[nt][h * 2 + 0] - mean_[h]) * rstd_[h] * g2.x + b2.x;
          float o1 = (att[nt][h * 2 + 1] - mean_[h]) * rstd_[h] * g2.y + b2.y;
          size_t off = (size_t)(rowbase + q0 + wm + r + h * 8) * 128 + c;
          *(float2*)&out[off] = make_float2(o0, o1);
        }
      }
    }
    __syncthreads();   // protect SCR + smem before next half
  }
}

// ---------------- launch ----------------
extern "C" void kernel_launch(void* const* d_in, const int* in_sizes, int n_in,
                              void* d_out, int out_size) {
  const float* x     = (const float*)d_in[0];
  const float* Wq    = (const float*)d_in[1];
  const float* Wk    = (const float*)d_in[2];
  const float* Wv    = (const float*)d_in[3];
  const float* Wq_ss = (const float*)d_in[4];
  const float* Wk_ss = (const float*)d_in[5];
  const float* Wv_ss = (const float*)d_in[6];
  const float* Wq_se = (const float*)d_in[7];
  const float* Wk_se = (const float*)d_in[8];
  const float* Wv_se = (const float*)d_in[9];
  const float* g_in  = (const float*)d_in[10];
  const float* b_in  = (const float*)d_in[11];
  const float* g_ss  = (const float*)d_in[12];
  const float* b_ss  = (const float*)d_in[13];
  const float* g_se  = (const float*)d_in[14];
  const float* b_se  = (const float*)d_in[15];
  const float* g_out = (const float*)d_in[16];
  const float* b_out = (const float*)d_in[17];
  const float* lq1   = (const float*)d_in[18];
  const float* lq2   = (const float*)d_in[19];
  const float* lk1   = (const float*)d_in[20];
  const float* lk2   = (const float*)d_in[21];

  static bool attr_set = false;
  if (!attr_set) {
    cudaFuncSetAttribute(proj_mma_kernel, cudaFuncAttributeMaxDynamicSharedMemorySize,
                         PROJ_SMEM);
    cudaFuncSetAttribute(attn_mma_kernel, cudaFuncAttributeMaxDynamicSharedMemorySize,
                         ATTN_SMEM);
    attr_set = true;
  }

  WPrepParams wp;
  wp.W[0] = Wq_ss; wp.W[1] = Wq; wp.W[2] = Wq_se;
  wp.W[3] = Wk_ss; wp.W[4] = Wk; wp.W[5] = Wk_se;
  wp.W[6] = Wv_ss; wp.W[7] = Wv; wp.W[8] = Wv_se;
  wp.lq1 = lq1; wp.lq2 = lq2; wp.lk1 = lk1; wp.lk2 = lk2;
  wprep_kernel<<<dim3(32, 4, 9), dim3(32, 32)>>>(wp);

  NormParams np;
  np.x = x;
  np.g[0] = g_ss; np.g[1] = g_in; np.g[2] = g_se;
  np.b[0] = b_ss; np.b[1] = b_in; np.b[2] = b_se;
  norm_split_kernel<<<NROW / 8, dim3(32, 8)>>>(np);

  proj_mma_kernel<<<dim3(144, 3, 2), 256, PROJ_SMEM>>>();

  attn_mma_kernel<<<dim3(18, 8), 256, ATTN_SMEM>>>(g_out, b_out, (float*)d_out);
}

// round 16
// speedup vs baseline: 1.0178x; 1.0178x over previous
#include <cuda_runtime.h>
#include <cuda_bf16.h>
#include <cstdint>
#include <cstddef>

constexpr int Bn = 8;
constexpr int Tn = 2304;
constexpr int NROW = Bn * Tn;          // 18432
constexpr float LAMBDA_INIT_F = 0.6192834728526787f;
constexpr float QSCALE = 0.18033688011112042f;   // (1/8) * log2(e)

typedef unsigned long long ull;

__device__ float g_lam;
__device__ __align__(16) __nv_bfloat16 g_xh[NROW * 1024];
__device__ __align__(16) __nv_bfloat16 g_xl[NROW * 1024];
__device__ __align__(16) __nv_bfloat16 g_wh[9 * 128 * 1024];
__device__ __align__(16) __nv_bfloat16 g_wl[9 * 128 * 1024];
__device__ __align__(16) __nv_bfloat16 g_qh[NROW * 128];
__device__ __align__(16) __nv_bfloat16 g_ql[NROW * 128];
__device__ __align__(16) __nv_bfloat16 g_kh[NROW * 128];
__device__ __align__(16) __nv_bfloat16 g_kl[NROW * 128];
__device__ __align__(16) __nv_bfloat16 g_vh[NROW * 128];
__device__ __align__(16) __nv_bfloat16 g_vl[NROW * 128];

__device__ __forceinline__ float fast_exp2(float x) {
  x = fmaxf(x, -125.0f);
  float t = x + 12582912.0f;
  int e = __float_as_int(t) - 0x4B400000;
  float f = x - (t - 12582912.0f);
  float p =        1.3333558e-3f;
  p = fmaf(p, f,   9.6181291e-3f);
  p = fmaf(p, f,   5.5504109e-2f);
  p = fmaf(p, f,   2.4022651e-1f);
  p = fmaf(p, f,   6.9314718e-1f);
  p = fmaf(p, f,   1.0f);
  return __int_as_float(__float_as_int(p) + (e << 23));
}

__device__ __forceinline__ uint32_t smem_u32(const void* p) {
  uint32_t a;
  asm("{ .reg .u64 t; cvta.to.shared.u64 t, %1; cvt.u32.u64 %0, t; }" : "=r"(a) : "l"(p));
  return a;
}
__device__ __forceinline__ uint32_t sw128(uint32_t off) {
  return off ^ ((off >> 3) & 0x70);
}
__device__ __forceinline__ void cpasync16(uint32_t dst, const void* src) {
  asm volatile("cp.async.cg.shared.global [%0], [%1], 16;" :: "r"(dst), "l"(src));
}
__device__ __forceinline__ void cp_commit() {
  asm volatile("cp.async.commit_group;" ::: "memory");
}
__device__ __forceinline__ void cp_wait1() {
  asm volatile("cp.async.wait_group 1;" ::: "memory");
}
__device__ __forceinline__ void cp_wait0() {
  asm volatile("cp.async.wait_group 0;" ::: "memory");
}
__device__ __forceinline__ void ldsm4(uint32_t* r, uint32_t a) {
  asm volatile("ldmatrix.sync.aligned.m8n8.x4.shared.b16 {%0,%1,%2,%3}, [%4];"
               : "=r"(r[0]), "=r"(r[1]), "=r"(r[2]), "=r"(r[3]) : "r"(a));
}
__device__ __forceinline__ void ldsm4t(uint32_t* r, uint32_t a) {
  asm volatile("ldmatrix.sync.aligned.m8n8.x4.trans.shared.b16 {%0,%1,%2,%3}, [%4];"
               : "=r"(r[0]), "=r"(r[1]), "=r"(r[2]), "=r"(r[3]) : "r"(a));
}
__device__ __forceinline__ void mma16816(float* d, const uint32_t* a, uint32_t b0, uint32_t b1) {
  asm volatile(
      "mma.sync.aligned.m16n8k16.row.col.f32.bf16.bf16.f32 "
      "{%0,%1,%2,%3},{%4,%5,%6,%7},{%8,%9},{%0,%1,%2,%3};"
      : "+f"(d[0]), "+f"(d[1]), "+f"(d[2]), "+f"(d[3])
      : "r"(a[0]), "r"(a[1]), "r"(a[2]), "r"(a[3]), "r"(b0), "r"(b1));
}
__device__ __forceinline__ void hilo(float a, float b, uint32_t& h, uint32_t& l) {
  __nv_bfloat16 ha = __float2bfloat16_rn(a), hb = __float2bfloat16_rn(b);
  __nv_bfloat162 H; H.x = ha; H.y = hb;
  h = *(uint32_t*)&H;
  __nv_bfloat162 L;
  L.x = __float2bfloat16_rn(a - __bfloat162float(ha));
  L.y = __float2bfloat16_rn(b - __bfloat162float(hb));
  l = *(uint32_t*)&L;
}

// ---------------- LN + bf16 hi/lo split of x ----------------
struct NormParams {
  const float* x;
  const float* g[3];
  const float* b[3];
};

__global__ void norm_split_kernel(NormParams p) {
  int row = blockIdx.x * 8 + threadIdx.y;
  int t = row % Tn;
  int seg = t < 128 ? 0 : (t < 2176 ? 1 : 2);
  const float* __restrict__ gg = p.g[seg];
  const float* __restrict__ bb = p.b[seg];
  int lid = threadIdx.x;
  const float* xr = p.x + (size_t)row * 1024;

  float v[32];
  float s = 0.f, ss = 0.f;
#pragma unroll
  for (int i = 0; i < 8; i++) {
    float4 f = *(const float4*)&xr[i * 128 + lid * 4];
    v[i * 4 + 0] = f.x; v[i * 4 + 1] = f.y; v[i * 4 + 2] = f.z; v[i * 4 + 3] = f.w;
    s += f.x + f.y + f.z + f.w;
    ss += f.x * f.x + f.y * f.y + f.z * f.z + f.w * f.w;
  }
#pragma unroll
  for (int o = 16; o > 0; o >>= 1) {
    s += __shfl_xor_sync(0xffffffffu, s, o);
    ss += __shfl_xor_sync(0xffffffffu, ss, o);
  }
  float mean = s * (1.0f / 1024.0f);
  float var = fmaf(-mean, mean, ss * (1.0f / 1024.0f));
  float rstd = rsqrtf(var + 1e-5f);

  __nv_bfloat16* xh = g_xh + (size_t)row * 1024;
  __nv_bfloat16* xl = g_xl + (size_t)row * 1024;
#pragma unroll
  for (int i = 0; i < 8; i++) {
    int k = i * 128 + lid * 4;
    float4 gf = *(const float4*)&gg[k];
    float4 bf = *(const float4*)&bb[k];
    float a0 = (v[i * 4 + 0] - mean) * rstd * gf.x + bf.x;
    float a1 = (v[i * 4 + 1] - mean) * rstd * gf.y + bf.y;
    float a2 = (v[i * 4 + 2] - mean) * rstd * gf.z + bf.z;
    float a3 = (v[i * 4 + 3] - mean) * rstd * gf.w + bf.w;
    uint2 hp, lp;
    hilo(a0, a1, hp.x, lp.x);
    hilo(a2, a3, hp.y, lp.y);
    *(uint2*)&xh[k] = hp;
    *(uint2*)&xl[k] = lp;
  }
}

// ---------------- weight transpose + bf16 hi/lo split (+ fused lambda) ----------------
struct WPrepParams {
  const float* W[9];
  const float* lq1;
  const float* lq2;
  const float* lk1;
  const float* lk2;
};

__global__ void wprep_kernel(WPrepParams p) {
  __shared__ float tile[32][33];
  int mat = blockIdx.z;
  const float* __restrict__ W = p.W[mat];
  int kb = blockIdx.x * 32, nb = blockIdx.y * 32;
  int tx = threadIdx.x, ty = threadIdx.y;
  tile[ty][tx] = W[(size_t)(kb + ty) * 128 + nb + tx];
  __syncthreads();
  float v = tile[tx][ty];
  __nv_bfloat16 h = __float2bfloat16_rn(v);
  __nv_bfloat16 l = __float2bfloat16_rn(v - __bfloat162float(h));
  size_t o = (size_t)mat * 128 * 1024 + (size_t)(nb + ty) * 1024 + kb + tx;
  g_wh[o] = h;
  g_wl[o] = l;

  if (mat == 0 && blockIdx.x == 0 && blockIdx.y == 0 && ty == 0) {
    float a = p.lq1[tx] * p.lk1[tx] + p.lq1[tx + 32] * p.lk1[tx + 32];
    float c = p.lq2[tx] * p.lk2[tx] + p.lq2[tx + 32] * p.lk2[tx + 32];
#pragma unroll
    for (int off = 16; off > 0; off >>= 1) {
      a += __shfl_xor_sync(0xffffffffu, a, off);
      c += __shfl_xor_sync(0xffffffffu, c, off);
    }
    if (tx == 0) g_lam = expf(a) - expf(c) + LAMBDA_INIT_F;
  }
}

// ---------------- projection GEMM (unchanged R10) ----------------
constexpr int PB_AH = 0;
constexpr int PB_AL = 16384;
constexpr int PB_BH = 32768;
constexpr int PB_BL = 40960;
constexpr int PBUF = 49152;
constexpr int PROJ_SMEM = 2 * PBUF;   // 98304

__global__ __launch_bounds__(256, 2) void proj_mma_kernel() {
  extern __shared__ char smem[];
  uint32_t sb = smem_u32(smem);
  const int tid = threadIdx.x;
  const int rt = blockIdx.x, mat = blockIdx.y, nh = blockIdx.z;
  const int row0 = rt * 128;
  const int t0 = row0 % Tn;
  const int seg = t0 < 128 ? 0 : (t0 < 2176 ? 1 : 2);
  const size_t wbase = (size_t)(mat * 3 + seg) * 128 * 1024 + (size_t)nh * 64 * 1024;
  const __nv_bfloat16* __restrict__ Ah_g = g_xh + (size_t)row0 * 1024;
  const __nv_bfloat16* __restrict__ Al_g = g_xl + (size_t)row0 * 1024;
  const __nv_bfloat16* __restrict__ Bh_g = g_wh + wbase;
  const __nv_bfloat16* __restrict__ Bl_g = g_wl + wbase;

  const int lane = tid & 31;
  const int wid = tid >> 5;
  const int wm = (wid & 3) * 32;
  const int wn = (wid >> 2) * 32;
  const int lrow = lane & 7;
  const int sel = lane >> 3;
  const int selm = (sel & 1) * 8;
  const int selc = (sel >> 1) * 16;

  float acc[2][4][4];
#pragma unroll
  for (int mt = 0; mt < 2; mt++)
#pragma unroll
    for (int nt = 0; nt < 4; nt++)
#pragma unroll
      for (int j = 0; j < 4; j++) acc[mt][nt][j] = 0.f;

  auto issue = [&](int ch, int b) {
    const int k0 = ch * 64;
    const uint32_t dst = sb + b * PBUF;
#pragma unroll
    for (int it = 0; it < 4; it++) {
      int i = tid + it * 256;
      int r = i >> 3, c = i & 7;
      uint32_t d = sw128((uint32_t)(r * 128 + c * 16));
      size_t go = (size_t)r * 1024 + k0 + c * 8;
      cpasync16(dst + PB_AH + d, Ah_g + go);
      cpasync16(dst + PB_AL + d, Al_g + go);
    }
#pragma unroll
    for (int it = 0; it < 2; it++) {
      int i = tid + it * 256;
      int r = i >> 3, c = i & 7;
      uint32_t d = sw128((uint32_t)(r * 128 + c * 16));
      size_t go = (size_t)r * 1024 + k0 + c * 8;
      cpasync16(dst + PB_BH + d, Bh_g + go);
      cpasync16(dst + PB_BL + d, Bl_g + go);
    }
  };

  issue(0, 0);
  cp_commit();

  for (int ch = 0; ch < 16; ch++) {
    if (ch + 1 < 16) {
      issue(ch + 1, (ch + 1) & 1);
      cp_commit();
      cp_wait1();
    } else {
      cp_wait0();
    }
    __syncthreads();

    const uint32_t base = sb + (ch & 1) * PBUF;
#pragma unroll
    for (int ks = 0; ks < 4; ks++) {
      const int colb = ks * 32 + selc;
      uint32_t ah[2][4], al[2][4];
#pragma unroll
      for (int mt = 0; mt < 2; mt++) {
        int r = wm + mt * 16 + selm + lrow;
        uint32_t off = sw128((uint32_t)(r * 128 + colb));
        ldsm4(ah[mt], base + PB_AH + off);
        ldsm4(al[mt], base + PB_AL + off);
      }
      uint32_t bh[4][2], bl[4][2];
#pragma unroll
      for (int np = 0; np < 2; np++) {
        int r = wn + np * 16 + selm + lrow;
        uint32_t off = sw128((uint32_t)(r * 128 + colb));
        uint32_t t4[4];
        ldsm4(t4, base + PB_BH + off);
        bh[2 * np][0] = t4[0]; bh[2 * np][1] = t4[2];
        bh[2 * np + 1][0] = t4[1]; bh[2 * np + 1][1] = t4[3];
        ldsm4(t4, base + PB_BL + off);
        bl[2 * np][0] = t4[0]; bl[2 * np][1] = t4[2];
        bl[2 * np + 1][0] = t4[1]; bl[2 * np + 1][1] = t4[3];
      }
#pragma unroll
      for (int mt = 0; mt < 2; mt++)
#pragma unroll
        for (int nt = 0; nt < 4; nt++) {
          mma16816(acc[mt][nt], ah[mt], bh[nt][0], bh[nt][1]);
          mma16816(acc[mt][nt], ah[mt], bl[nt][0], bl[nt][1]);
          mma16816(acc[mt][nt], al[mt], bh[nt][0], bh[nt][1]);
        }
    }
    __syncthreads();
  }

  __nv_bfloat16* __restrict__ oh = (mat == 0) ? g_qh : (mat == 1) ? g_kh : g_vh;
  __nv_bfloat16* __restrict__ ol = (mat == 0) ? g_ql : (mat == 1) ? g_kl : g_vl;
  const int orow = lane >> 2, ocol = (lane & 3) * 2;
#pragma unroll
  for (int mt = 0; mt < 2; mt++)
#pragma unroll
    for (int nt = 0; nt < 4; nt++) {
      int r = row0 + wm + mt * 16 + orow;
      int c = nh * 64 + wn + nt * 8 + ocol;
      uint32_t h0, l0, h1, l1;
      hilo(acc[mt][nt][0], acc[mt][nt][1], h0, l0);
      hilo(acc[mt][nt][2], acc[mt][nt][3], h1, l1);
      *(uint32_t*)&oh[(size_t)r * 128 + c] = h0;
      *(uint32_t*)&ol[(size_t)r * 128 + c] = l0;
      *(uint32_t*)&oh[(size_t)(r + 8) * 128 + c] = h1;
      *(uint32_t*)&ol[(size_t)(r + 8) * 128 + c] = l1;
    }
}

// ---------------- tensor-core dual flash attention (exact R13) ----------------
constexpr int KVBUF = 65536;              // Kh(2x8K) Kl(2x8K) Vh(2x8K) Vl(2x8K)
constexpr int AOFF_Q   = 131072;          // Qh d0-63, Qh d64-127, Ql d0-63, Ql d64-127
constexpr int AOFF_SCR = 163840;          // 64 x 132 f32 = 33792 B
constexpr int ATTN_SMEM = 197632;

__global__ __launch_bounds__(256, 1) void attn_mma_kernel(
    const float* __restrict__ gam, const float* __restrict__ bet,
    float* __restrict__ out) {
  extern __shared__ char smem[];
  uint32_t sb = smem_u32(smem);
  float* SCR = (float*)(smem + AOFF_SCR);

  const int tid = threadIdx.x;
  const int lane = tid & 31;
  const int wid = tid >> 5;
  const int wm = (wid & 3) * 16;
  const int m = wid >> 2;       // map 0/1
  const int lrow = lane & 7;
  const int sel = lane >> 3;
  const int selm = (sel & 1) * 8;
  const int selc = (sel >> 1) * 16;
  const int r = lane >> 2;
  const int cq = (lane & 3) * 2;

  const int rowbase = (int)blockIdx.y * Tn;
  const float lam = g_lam;

  auto issueKV = [&](int kt, int b) {
    const int k0g = kt * 64;
    const uint32_t dst = sb + b * KVBUF;
#pragma unroll
    for (int it = 0; it < 16; it++) {
      int idx = tid + it * 256;
      int part = idx >> 9;
      int j = idx & 511;
      int key = j >> 3, c = j & 7;
      uint32_t so = (uint32_t)part * 8192 + sw128((uint32_t)(key * 128 + c * 16));
      size_t go = (size_t)(rowbase + k0g + key) * 128 + (part & 1) * 64 + c * 8;
      const __nv_bfloat16* src =
          (part < 2) ? g_kh : (part < 4) ? g_kl : (part < 6) ? g_vh : g_vl;
      cpasync16(dst + so, src + go);
    }
  };
  auto issueQ = [&](int q0) {
#pragma unroll
    for (int it = 0; it < 8; it++) {
      int idx = tid + it * 256;
      int part = idx >> 9;
      int j = idx & 511;
      int row = j >> 3, c = j & 7;
      uint32_t so = AOFF_Q + (uint32_t)part * 8192 + sw128((uint32_t)(row * 128 + c * 16));
      size_t go = (size_t)(rowbase + q0 + row) * 128 + (part & 1) * 64 + c * 8;
      const __nv_bfloat16* src = (part < 2) ? g_qh : g_ql;
      cpasync16(sb + so, src + go);
    }
  };

  for (int half = 0; half < 2; half++) {
    const int qt = half ? (35 - (int)blockIdx.x) : (int)blockIdx.x;
    const int q0 = qt * 64;

    float oacc[16][4];
    float mrow[2], lrow_s[2];
#pragma unroll
    for (int h = 0; h < 2; h++) { mrow[h] = -3.0e38f; lrow_s[h] = 0.f; }
#pragma unroll
    for (int nt = 0; nt < 16; nt++)
#pragma unroll
      for (int j = 0; j < 4; j++) oacc[nt][j] = 0.f;

    issueQ(q0);
    issueKV(0, 0);
    cp_commit();

    for (int kt = 0; kt <= qt; kt++) {
      if (kt < qt) {
        issueKV(kt + 1, (kt + 1) & 1);
        cp_commit();
        cp_wait1();
      } else {
        cp_wait0();
      }
      __syncthreads();   // A: buffers ready

      const uint32_t buf = sb + (kt & 1) * KVBUF;
      const int k0 = kt * 64;

      // ---- S = Q K^T for this warp's map: 16 rows x 64 keys ----
      float sacc[8][4];
#pragma unroll
      for (int nt = 0; nt < 8; nt++)
#pragma unroll
        for (int j = 0; j < 4; j++) sacc[nt][j] = 0.f;

      {
        const uint32_t Qh = sb + AOFF_Q + m * 8192;
        const uint32_t Ql = sb + AOFF_Q + 16384 + m * 8192;
        const uint32_t Kh = buf + m * 8192;
        const uint32_t Kl = buf + 16384 + m * 8192;
#pragma unroll
        for (int ks = 0; ks < 4; ks++) {
          const int colb = ks * 32 + selc;
          uint32_t aoff = sw128((uint32_t)((wm + selm + lrow) * 128 + colb));
          uint32_t qh[4], ql[4];
          ldsm4(qh, Qh + aoff);
          ldsm4(ql, Ql + aoff);
          uint32_t bh[8][2], bl[8][2];
#pragma unroll
          for (int np = 0; np < 4; np++) {
            uint32_t boff = sw128((uint32_t)((np * 16 + selm + lrow) * 128 + colb));
            uint32_t t4[4];
            ldsm4(t4, Kh + boff);
            bh[2 * np][0] = t4[0]; bh[2 * np][1] = t4[2];
            bh[2 * np + 1][0] = t4[1]; bh[2 * np + 1][1] = t4[3];
            ldsm4(t4, Kl + boff);
            bl[2 * np][0] = t4[0]; bl[2 * np][1] = t4[2];
            bl[2 * np + 1][0] = t4[1]; bl[2 * np + 1][1] = t4[3];
          }
#pragma unroll
          for (int nt = 0; nt < 8; nt++) {
            mma16816(sacc[nt], qh, bh[nt][0], bh[nt][1]);
            mma16816(sacc[nt], ql, bh[nt][0], bh[nt][1]);
            mma16816(sacc[nt], qh, bl[nt][0], bl[nt][1]);
          }
        }
      }

      // ---- warp-local softmax ----
      const bool diag = (kt == qt);
      float mx[2] = {-3.0e38f, -3.0e38f};
#pragma unroll
      for (int nt = 0; nt < 8; nt++)
#pragma unroll
        for (int h = 0; h < 2; h++)
#pragma unroll
          for (int j = 0; j < 2; j++) {
            float v = sacc[nt][h * 2 + j] * QSCALE;
            if (diag && (k0 + nt * 8 + cq + j) > (q0 + wm + r + h * 8)) v = -3.0e38f;
            sacc[nt][h * 2 + j] = v;
            mx[h] = fmaxf(mx[h], v);
          }
#pragma unroll
      for (int h = 0; h < 2; h++) {
        mx[h] = fmaxf(mx[h], __shfl_xor_sync(0xffffffffu, mx[h], 1));
        mx[h] = fmaxf(mx[h], __shfl_xor_sync(0xffffffffu, mx[h], 2));
      }

      float alpha[2], lsum[2] = {0.f, 0.f};
#pragma unroll
      for (int h = 0; h < 2; h++) {
        float mn = fmaxf(mrow[h], mx[h]);
        alpha[h] = fast_exp2(mrow[h] - mn);
        mrow[h] = mn;
      }

      uint32_t pfh[4][4], pfl[4][4];
#pragma unroll
      for (int nt = 0; nt < 8; nt++)
#pragma unroll
        for (int h = 0; h < 2; h++) {
          float p0 = fast_exp2(sacc[nt][h * 2 + 0] - mrow[h]);
          float p1 = fast_exp2(sacc[nt][h * 2 + 1] - mrow[h]);
          lsum[h] += p0 + p1;
          sacc[nt][h * 2 + 0] = p0;
          sacc[nt][h * 2 + 1] = p1;
        }
#pragma unroll
      for (int ks = 0; ks < 4; ks++) {
        hilo(sacc[2 * ks][0], sacc[2 * ks][1], pfh[ks][0], pfl[ks][0]);
        hilo(sacc[2 * ks][2], sacc[2 * ks][3], pfh[ks][1], pfl[ks][1]);
        hilo(sacc[2 * ks + 1][0], sacc[2 * ks + 1][1], pfh[ks][2], pfl[ks][2]);
        hilo(sacc[2 * ks + 1][2], sacc[2 * ks + 1][3], pfh[ks][3], pfl[ks][3]);
      }
#pragma unroll
      for (int h = 0; h < 2; h++) {
        lsum[h] += __shfl_xor_sync(0xffffffffu, lsum[h], 1);
        lsum[h] += __shfl_xor_sync(0xffffffffu, lsum[h], 2);
        lrow_s[h] = lrow_s[h] * alpha[h] + lsum[h];
      }
#pragma unroll
      for (int nt = 0; nt < 16; nt++) {
        oacc[nt][0] *= alpha[0];
        oacc[nt][1] *= alpha[0];
        oacc[nt][2] *= alpha[1];
        oacc[nt][3] *= alpha[1];
      }

      // ---- O += P V ----
#pragma unroll
      for (int ks = 0; ks < 4; ks++) {
        const int vrow = ks * 16 + selm + lrow;
#pragma unroll
        for (int np = 0; np < 8; np++) {
          const int part = np >> 2;
          const uint32_t boff = (uint32_t)part * 8192 +
              sw128((uint32_t)(vrow * 128 + (np & 3) * 32 + selc));
          uint32_t vh4[4], vl4[4];
          ldsm4t(vh4, buf + 32768 + boff);
          ldsm4t(vl4, buf + 49152 + boff);
#pragma unroll
          for (int e = 0; e < 2; e++) {
            float* d = oacc[2 * np + e];
            mma16816(d, pfh[ks], vh4[2 * e], vh4[2 * e + 1]);
            mma16816(d, pfl[ks], vh4[2 * e], vh4[2 * e + 1]);
            mma16816(d, pfh[ks], vl4[2 * e], vl4[2 * e + 1]);
          }
        }
      }
      __syncthreads();   // D: protect KV buffer reuse
    }

    // ---- epilogue: cross-map combine + output LN ----
    if (m == 1) {
      float inv2[2];
#pragma unroll
      for (int h = 0; h < 2; h++) inv2[h] = lam / lrow_s[h];
#pragma unroll
      for (int nt = 0; nt < 16; nt++)
#pragma unroll
        for (int h = 0; h < 2; h++) {
          int rr = wm + r + h * 8;
          SCR[rr * 132 + nt * 8 + cq]     = oacc[nt][h * 2 + 0] * inv2[h];
          SCR[rr * 132 + nt * 8 + cq + 1] = oacc[nt][h * 2 + 1] * inv2[h];
        }
    }
    __syncthreads();
    if (m == 0) {
      float inv1[2];
#pragma unroll
      for (int h = 0; h < 2; h++) inv1[h] = 1.0f / lrow_s[h];
      float att[16][4];
      float rs[2] = {0.f, 0.f};
#pragma unroll
      for (int nt = 0; nt < 16; nt++)
#pragma unroll
        for (int h = 0; h < 2; h++) {
          int rr = wm + r + h * 8;
          float a0 = oacc[nt][h * 2 + 0] * inv1[h] - SCR[rr * 132 + nt * 8 + cq];
          float a1 = oacc[nt][h * 2 + 1] * inv1[h] - SCR[rr * 132 + nt * 8 + cq + 1];
          att[nt][h * 2 + 0] = a0;
          att[nt][h * 2 + 1] = a1;
          rs[h] += a0 + a1;
        }
#pragma unroll
      for (int h = 0; h < 2; h++) {
        rs[h] += __shfl_xor_sync(0xffffffffu, rs[h], 1);
        rs[h] += __shfl_xor_sync(0xffffffffu, rs[h], 2);
      }
      float mean_[2];
#pragma unroll
      for (int h = 0; h < 2; h++) mean_[h] = rs[h] * (1.0f / 128.0f);

      float vs[2] = {0.f, 0.f};
#pragma unroll
      for (int nt = 0; nt < 16; nt++)
#pragma unroll
        for (int h = 0; h < 2; h++)
#pragma unroll
          for (int j = 0; j < 2; j++) {
            float a = att[nt][h * 2 + j] - mean_[h];
            vs[h] += a * a;
          }
#pragma unroll
      for (int h = 0; h < 2; h++) {
        vs[h] += __shfl_xor_sync(0xffffffffu, vs[h], 1);
        vs[h] += __shfl_xor_sync(0xffffffffu, vs[h], 2);
      }
      float rstd_[2];
#pragma unroll
      for (int h = 0; h < 2; h++)
        rstd_[h] = rsqrtf(vs[h] * (1.0f / 128.0f) + 1e-5f);

#pragma unroll
      for (int nt = 0; nt < 16; nt++) {
        int c = nt * 8 + cq;
        float2 g2 = *(const float2*)&gam[c];
        float2 b2 = *(const float2*)&bet[c];
#pragma unroll
        for (int h = 0; h < 2; h++) {
          float o0 = (att[nt][h * 2 + 0] - mean_[h]) * rstd_[h] * g2.x + b2.x;
          float o1 = (att[nt][h * 2 + 1] - mean_[h]) * rstd_[h] * g2.y + b2.y;
          size_t off = (size_t)(rowbase + q0 + wm + r + h * 8) * 128 + c;
          *(float2*)&out[off] = make_float2(o0, o1);
        }
      }
    }
    __syncthreads();   // protect SCR + smem before next half
  }
}

// ---------------- launch ----------------
extern "C" void kernel_launch(void* const* d_in, const int* in_sizes, int n_in,
                              void* d_out, int out_size) {
  const float* x     = (const float*)d_in[0];
  const float* Wq    = (const float*)d_in[1];
  const float* Wk    = (const float*)d_in[2];
  const float* Wv    = (const float*)d_in[3];
  const float* Wq_ss = (const float*)d_in[4];
  const float* Wk_ss = (const float*)d_in[5];
  const float* Wv_ss = (const float*)d_in[6];
  const float* Wq_se = (const float*)d_in[7];
  const float* Wk_se = (const float*)d_in[8];
  const float* Wv_se = (const float*)d_in[9];
  const float* g_in  = (const float*)d_in[10];
  const float* b_in  = (const float*)d_in[11];
  const float* g_ss  = (const float*)d_in[12];
  const float* b_ss  = (const float*)d_in[13];
  const float* g_se  = (const float*)d_in[14];
  const float* b_se  = (const float*)d_in[15];
  const float* g_out = (const float*)d_in[16];
  const float* b_out = (const float*)d_in[17];
  const float* lq1   = (const float*)d_in[18];
  const float* lq2   = (const float*)d_in[19];
  const float* lk1   = (const float*)d_in[20];
  const float* lk2   = (const float*)d_in[21];

  static bool attr_set = false;
  if (!attr_set) {
    cudaFuncSetAttribute(proj_mma_kernel, cudaFuncAttributeMaxDynamicSharedMemorySize,
                         PROJ_SMEM);
    cudaFuncSetAttribute(attn_mma_kernel, cudaFuncAttributeMaxDynamicSharedMemorySize,
                         ATTN_SMEM);
    attr_set = true;
  }

  WPrepParams wp;
  wp.W[0] = Wq_ss; wp.W[1] = Wq; wp.W[2] = Wq_se;
  wp.W[3] = Wk_ss; wp.W[4] = Wk; wp.W[5] = Wk_se;
  wp.W[6] = Wv_ss; wp.W[7] = Wv; wp.W[8] = Wv_se;
  wp.lq1 = lq1; wp.lq2 = lq2; wp.lk1 = lk1; wp.lk2 = lk2;
  wprep_kernel<<<dim3(32, 4, 9), dim3(32, 32)>>>(wp);

  NormParams np;
  np.x = x;
  np.g[0] = g_ss; np.g[1] = g_in; np.g[2] = g_se;
  np.b[0] = b_ss; np.b[1] = b_in; np.b[2] = b_se;
  norm_split_kernel<<<NROW / 8, dim3(32, 8)>>>(np);

  proj_mma_kernel<<<dim3(144, 3, 2), 256, PROJ_SMEM>>>();

  attn_mma_kernel<<<dim3(18, 8), 256, ATTN_SMEM>>>(g_out, b_out, (float*)d_out);
}

// round 17
// speedup vs baseline: 1.0324x; 1.0143x over previous
#include <cuda_runtime.h>
#include <cuda_bf16.h>
#include <cstdint>
#include <cstddef>

constexpr int Bn = 8;
constexpr int Tn = 2304;
constexpr int NROW = Bn * Tn;          // 18432
constexpr float LAMBDA_INIT_F = 0.6192834728526787f;
constexpr float QSCALE = 0.18033688011112042f;   // (1/8) * log2(e)

typedef unsigned long long ull;

__device__ float g_lam;
__device__ __align__(16) __nv_bfloat16 g_xh[NROW * 1024];
__device__ __align__(16) __nv_bfloat16 g_xl[NROW * 1024];
__device__ __align__(16) __nv_bfloat16 g_wh[9 * 128 * 1024];
__device__ __align__(16) __nv_bfloat16 g_wl[9 * 128 * 1024];
__device__ __align__(16) __nv_bfloat16 g_qh[NROW * 128];
__device__ __align__(16) __nv_bfloat16 g_ql[NROW * 128];
__device__ __align__(16) __nv_bfloat16 g_kh[NROW * 128];
__device__ __align__(16) __nv_bfloat16 g_kl[NROW * 128];
__device__ __align__(16) __nv_bfloat16 g_vh[NROW * 128];
__device__ __align__(16) __nv_bfloat16 g_vl[NROW * 128];

__device__ __forceinline__ float fast_exp2(float x) {
  x = fmaxf(x, -125.0f);
  float t = x + 12582912.0f;
  int e = __float_as_int(t) - 0x4B400000;
  float f = x - (t - 12582912.0f);
  float p =        1.3333558e-3f;
  p = fmaf(p, f,   9.6181291e-3f);
  p = fmaf(p, f,   5.5504109e-2f);
  p = fmaf(p, f,   2.4022651e-1f);
  p = fmaf(p, f,   6.9314718e-1f);
  p = fmaf(p, f,   1.0f);
  return __int_as_float(__float_as_int(p) + (e << 23));
}

__device__ __forceinline__ uint32_t smem_u32(const void* p) {
  uint32_t a;
  asm("{ .reg .u64 t; cvta.to.shared.u64 t, %1; cvt.u32.u64 %0, t; }" : "=r"(a) : "l"(p));
  return a;
}
__device__ __forceinline__ uint32_t sw128(uint32_t off) {
  return off ^ ((off >> 3) & 0x70);
}
__device__ __forceinline__ void cpasync16(uint32_t dst, const void* src) {
  asm volatile("cp.async.cg.shared.global [%0], [%1], 16;" :: "r"(dst), "l"(src));
}
__device__ __forceinline__ void cp_commit() {
  asm volatile("cp.async.commit_group;" ::: "memory");
}
__device__ __forceinline__ void cp_wait1() {
  asm volatile("cp.async.wait_group 1;" ::: "memory");
}
__device__ __forceinline__ void cp_wait0() {
  asm volatile("cp.async.wait_group 0;" ::: "memory");
}
__device__ __forceinline__ void ldsm4(uint32_t* r, uint32_t a) {
  asm volatile("ldmatrix.sync.aligned.m8n8.x4.shared.b16 {%0,%1,%2,%3}, [%4];"
               : "=r"(r[0]), "=r"(r[1]), "=r"(r[2]), "=r"(r[3]) : "r"(a));
}
__device__ __forceinline__ void ldsm4t(uint32_t* r, uint32_t a) {
  asm volatile("ldmatrix.sync.aligned.m8n8.x4.trans.shared.b16 {%0,%1,%2,%3}, [%4];"
               : "=r"(r[0]), "=r"(r[1]), "=r"(r[2]), "=r"(r[3]) : "r"(a));
}
__device__ __forceinline__ void mma16816(float* d, const uint32_t* a, uint32_t b0, uint32_t b1) {
  asm volatile(
      "mma.sync.aligned.m16n8k16.row.col.f32.bf16.bf16.f32 "
      "{%0,%1,%2,%3},{%4,%5,%6,%7},{%8,%9},{%0,%1,%2,%3};"
      : "+f"(d[0]), "+f"(d[1]), "+f"(d[2]), "+f"(d[3])
      : "r"(a[0]), "r"(a[1]), "r"(a[2]), "r"(a[3]), "r"(b0), "r"(b1));
}
// round-to-nearest hi/lo split (prep kernels)
__device__ __forceinline__ void hilo(float a, float b, uint32_t& h, uint32_t& l) {
  __nv_bfloat16 ha = __float2bfloat16_rn(a), hb = __float2bfloat16_rn(b);
  __nv_bfloat162 H; H.x = ha; H.y = hb;
  h = *(uint32_t*)&H;
  __nv_bfloat162 L;
  L.x = __float2bfloat16_rn(a - __bfloat162float(ha));
  L.y = __float2bfloat16_rn(b - __bfloat162float(hb));
  l = *(uint32_t*)&L;
}
// truncation-based hi/lo split (fast path, attn P conversion)
__device__ __forceinline__ void hilo_t(float a, float b, uint32_t& h, uint32_t& l) {
  uint32_t au = __float_as_uint(a), bu = __float_as_uint(b);
  asm("prmt.b32 %0, %1, %2, 0x7632;" : "=r"(h) : "r"(au), "r"(bu));
  float la = a - __uint_as_float(au & 0xFFFF0000u);
  float lb = b - __uint_as_float(bu & 0xFFFF0000u);
  asm("cvt.rn.satfinite.bf16x2.f32 %0, %1, %2;" : "=r"(l) : "f"(lb), "f"(la));
}

// ---------------- LN + bf16 hi/lo split of x ----------------
struct NormParams {
  const float* x;
  const float* g[3];
  const float* b[3];
};

__global__ void norm_split_kernel(NormParams p) {
  int row = blockIdx.x * 8 + threadIdx.y;
  int t = row % Tn;
  int seg = t < 128 ? 0 : (t < 2176 ? 1 : 2);
  const float* __restrict__ gg = p.g[seg];
  const float* __restrict__ bb = p.b[seg];
  int lid = threadIdx.x;
  const float* xr = p.x + (size_t)row * 1024;

  float v[32];
  float s = 0.f, ss = 0.f;
#pragma unroll
  for (int i = 0; i < 8; i++) {
    float4 f = *(const float4*)&xr[i * 128 + lid * 4];
    v[i * 4 + 0] = f.x; v[i * 4 + 1] = f.y; v[i * 4 + 2] = f.z; v[i * 4 + 3] = f.w;
    s += f.x + f.y + f.z + f.w;
    ss += f.x * f.x + f.y * f.y + f.z * f.z + f.w * f.w;
  }
#pragma unroll
  for (int o = 16; o > 0; o >>= 1) {
    s += __shfl_xor_sync(0xffffffffu, s, o);
    ss += __shfl_xor_sync(0xffffffffu, ss, o);
  }
  float mean = s * (1.0f / 1024.0f);
  float var = fmaf(-mean, mean, ss * (1.0f / 1024.0f));
  float rstd = rsqrtf(var + 1e-5f);

  __nv_bfloat16* xh = g_xh + (size_t)row * 1024;
  __nv_bfloat16* xl = g_xl + (size_t)row * 1024;
#pragma unroll
  for (int i = 0; i < 8; i++) {
    int k = i * 128 + lid * 4;
    float4 gf = *(const float4*)&gg[k];
    float4 bf = *(const float4*)&bb[k];
    float a0 = (v[i * 4 + 0] - mean) * rstd * gf.x + bf.x;
    float a1 = (v[i * 4 + 1] - mean) * rstd * gf.y + bf.y;
    float a2 = (v[i * 4 + 2] - mean) * rstd * gf.z + bf.z;
    float a3 = (v[i * 4 + 3] - mean) * rstd * gf.w + bf.w;
    uint2 hp, lp;
    hilo(a0, a1, hp.x, lp.x);
    hilo(a2, a3, hp.y, lp.y);
    *(uint2*)&xh[k] = hp;
    *(uint2*)&xl[k] = lp;
  }
}

// ---------------- weight transpose + bf16 hi/lo split (+ fused lambda) ----------------
struct WPrepParams {
  const float* W[9];
  const float* lq1;
  const float* lq2;
  const float* lk1;
  const float* lk2;
};

__global__ void wprep_kernel(WPrepParams p) {
  __shared__ float tile[32][33];
  int mat = blockIdx.z;
  const float* __restrict__ W = p.W[mat];
  int kb = blockIdx.x * 32, nb = blockIdx.y * 32;
  int tx = threadIdx.x, ty = threadIdx.y;
  tile[ty][tx] = W[(size_t)(kb + ty) * 128 + nb + tx];
  __syncthreads();
  float v = tile[tx][ty];
  __nv_bfloat16 h = __float2bfloat16_rn(v);
  __nv_bfloat16 l = __float2bfloat16_rn(v - __bfloat162float(h));
  size_t o = (size_t)mat * 128 * 1024 + (size_t)(nb + ty) * 1024 + kb + tx;
  g_wh[o] = h;
  g_wl[o] = l;

  if (mat == 0 && blockIdx.x == 0 && blockIdx.y == 0 && ty == 0) {
    float a = p.lq1[tx] * p.lk1[tx] + p.lq1[tx + 32] * p.lk1[tx + 32];
    float c = p.lq2[tx] * p.lk2[tx] + p.lq2[tx + 32] * p.lk2[tx + 32];
#pragma unroll
    for (int off = 16; off > 0; off >>= 1) {
      a += __shfl_xor_sync(0xffffffffu, a, off);
      c += __shfl_xor_sync(0xffffffffu, c, off);
    }
    if (tx == 0) g_lam = expf(a) - expf(c) + LAMBDA_INIT_F;
  }
}

// ---------------- projection GEMM (R10 + QSCALE folded into Q) ----------------
constexpr int PB_AH = 0;
constexpr int PB_AL = 16384;
constexpr int PB_BH = 32768;
constexpr int PB_BL = 40960;
constexpr int PBUF = 49152;
constexpr int PROJ_SMEM = 2 * PBUF;   // 98304

__global__ __launch_bounds__(256, 2) void proj_mma_kernel() {
  extern __shared__ char smem[];
  uint32_t sb = smem_u32(smem);
  const int tid = threadIdx.x;
  const int rt = blockIdx.x, mat = blockIdx.y, nh = blockIdx.z;
  const int row0 = rt * 128;
  const int t0 = row0 % Tn;
  const int seg = t0 < 128 ? 0 : (t0 < 2176 ? 1 : 2);
  const size_t wbase = (size_t)(mat * 3 + seg) * 128 * 1024 + (size_t)nh * 64 * 1024;
  const __nv_bfloat16* __restrict__ Ah_g = g_xh + (size_t)row0 * 1024;
  const __nv_bfloat16* __restrict__ Al_g = g_xl + (size_t)row0 * 1024;
  const __nv_bfloat16* __restrict__ Bh_g = g_wh + wbase;
  const __nv_bfloat16* __restrict__ Bl_g = g_wl + wbase;

  const int lane = tid & 31;
  const int wid = tid >> 5;
  const int wm = (wid & 3) * 32;
  const int wn = (wid >> 2) * 32;
  const int lrow = lane & 7;
  const int sel = lane >> 3;
  const int selm = (sel & 1) * 8;
  const int selc = (sel >> 1) * 16;

  float acc[2][4][4];
#pragma unroll
  for (int mt = 0; mt < 2; mt++)
#pragma unroll
    for (int nt = 0; nt < 4; nt++)
#pragma unroll
      for (int j = 0; j < 4; j++) acc[mt][nt][j] = 0.f;

  auto issue = [&](int ch, int b) {
    const int k0 = ch * 64;
    const uint32_t dst = sb + b * PBUF;
#pragma unroll
    for (int it = 0; it < 4; it++) {
      int i = tid + it * 256;
      int r = i >> 3, c = i & 7;
      uint32_t d = sw128((uint32_t)(r * 128 + c * 16));
      size_t go = (size_t)r * 1024 + k0 + c * 8;
      cpasync16(dst + PB_AH + d, Ah_g + go);
      cpasync16(dst + PB_AL + d, Al_g + go);
    }
#pragma unroll
    for (int it = 0; it < 2; it++) {
      int i = tid + it * 256;
      int r = i >> 3, c = i & 7;
      uint32_t d = sw128((uint32_t)(r * 128 + c * 16));
      size_t go = (size_t)r * 1024 + k0 + c * 8;
      cpasync16(dst + PB_BH + d, Bh_g + go);
      cpasync16(dst + PB_BL + d, Bl_g + go);
    }
  };

  issue(0, 0);
  cp_commit();

  for (int ch = 0; ch < 16; ch++) {
    if (ch + 1 < 16) {
      issue(ch + 1, (ch + 1) & 1);
      cp_commit();
      cp_wait1();
    } else {
      cp_wait0();
    }
    __syncthreads();

    const uint32_t base = sb + (ch & 1) * PBUF;
#pragma unroll
    for (int ks = 0; ks < 4; ks++) {
      const int colb = ks * 32 + selc;
      uint32_t ah[2][4], al[2][4];
#pragma unroll
      for (int mt = 0; mt < 2; mt++) {
        int r = wm + mt * 16 + selm + lrow;
        uint32_t off = sw128((uint32_t)(r * 128 + colb));
        ldsm4(ah[mt], base + PB_AH + off);
        ldsm4(al[mt], base + PB_AL + off);
      }
      uint32_t bh[4][2], bl[4][2];
#pragma unroll
      for (int np = 0; np < 2; np++) {
        int r = wn + np * 16 + selm + lrow;
        uint32_t off = sw128((uint32_t)(r * 128 + colb));
        uint32_t t4[4];
        ldsm4(t4, base + PB_BH + off);
        bh[2 * np][0] = t4[0]; bh[2 * np][1] = t4[2];
        bh[2 * np + 1][0] = t4[1]; bh[2 * np + 1][1] = t4[3];
        ldsm4(t4, base + PB_BL + off);
        bl[2 * np][0] = t4[0]; bl[2 * np][1] = t4[2];
        bl[2 * np + 1][0] = t4[1]; bl[2 * np + 1][1] = t4[3];
      }
#pragma unroll
      for (int mt = 0; mt < 2; mt++)
#pragma unroll
        for (int nt = 0; nt < 4; nt++) {
          mma16816(acc[mt][nt], ah[mt], bh[nt][0], bh[nt][1]);
          mma16816(acc[mt][nt], ah[mt], bl[nt][0], bl[nt][1]);
          mma16816(acc[mt][nt], al[mt], bh[nt][0], bh[nt][1]);
        }
    }
    __syncthreads();
  }

  __nv_bfloat16* __restrict__ oh = (mat == 0) ? g_qh : (mat == 1) ? g_kh : g_vh;
  __nv_bfloat16* __restrict__ ol = (mat == 0) ? g_ql : (mat == 1) ? g_kl : g_vl;
  const float oscale = (mat == 0) ? QSCALE : 1.0f;
  const int orow = lane >> 2, ocol = (lane & 3) * 2;
#pragma unroll
  for (int mt = 0; mt < 2; mt++)
#pragma unroll
    for (int nt = 0; nt < 4; nt++) {
      int r = row0 + wm + mt * 16 + orow;
      int c = nh * 64 + wn + nt * 8 + ocol;
      uint32_t h0, l0, h1, l1;
      hilo(acc[mt][nt][0] * oscale, acc[mt][nt][1] * oscale, h0, l0);
      hilo(acc[mt][nt][2] * oscale, acc[mt][nt][3] * oscale, h1, l1);
      *(uint32_t*)&oh[(size_t)r * 128 + c] = h0;
      *(uint32_t*)&ol[(size_t)r * 128 + c] = l0;
      *(uint32_t*)&oh[(size_t)(r + 8) * 128 + c] = h1;
      *(uint32_t*)&ol[(size_t)(r + 8) * 128 + c] = l1;
    }
}

// ---------------- tensor-core dual flash attention (R13 + ALU cuts) ----------------
constexpr int KVBUF = 65536;              // Kh(2x8K) Kl(2x8K) Vh(2x8K) Vl(2x8K)
constexpr int AOFF_Q   = 131072;          // Qh d0-63, Qh d64-127, Ql d0-63, Ql d64-127
constexpr int AOFF_SCR = 163840;          // 64 x 132 f32 = 33792 B
constexpr int ATTN_SMEM = 197632;

__global__ __launch_bounds__(256, 1) void attn_mma_kernel(
    const float* __restrict__ gam, const float* __restrict__ bet,
    float* __restrict__ out) {
  extern __shared__ char smem[];
  uint32_t sb = smem_u32(smem);
  float* SCR = (float*)(smem + AOFF_SCR);

  const int tid = threadIdx.x;
  const int lane = tid & 31;
  const int wid = tid >> 5;
  const int wm = (wid & 3) * 16;
  const int m = wid >> 2;       // map 0/1
  const int lrow = lane & 7;
  const int sel = lane >> 3;
  const int selm = (sel & 1) * 8;
  const int selc = (sel >> 1) * 16;
  const int r = lane >> 2;
  const int cq = (lane & 3) * 2;

  const int rowbase = (int)blockIdx.y * Tn;
  const float lam = g_lam;

  auto issueKV = [&](int kt, int b) {
    const int k0g = kt * 64;
    const uint32_t dst = sb + b * KVBUF;
#pragma unroll
    for (int it = 0; it < 16; it++) {
      int idx = tid + it * 256;
      int part = idx >> 9;
      int j = idx & 511;
      int key = j >> 3, c = j & 7;
      uint32_t so = (uint32_t)part * 8192 + sw128((uint32_t)(key * 128 + c * 16));
      size_t go = (size_t)(rowbase + k0g + key) * 128 + (part & 1) * 64 + c * 8;
      const __nv_bfloat16* src =
          (part < 2) ? g_kh : (part < 4) ? g_kl : (part < 6) ? g_vh : g_vl;
      cpasync16(dst + so, src + go);
    }
  };
  auto issueQ = [&](int q0) {
#pragma unroll
    for (int it = 0; it < 8; it++) {
      int idx = tid + it * 256;
      int part = idx >> 9;
      int j = idx & 511;
      int row = j >> 3, c = j & 7;
      uint32_t so = AOFF_Q + (uint32_t)part * 8192 + sw128((uint32_t)(row * 128 + c * 16));
      size_t go = (size_t)(rowbase + q0 + row) * 128 + (part & 1) * 64 + c * 8;
      const __nv_bfloat16* src = (part < 2) ? g_qh : g_ql;
      cpasync16(sb + so, src + go);
    }
  };

  for (int half = 0; half < 2; half++) {
    const int qt = half ? (35 - (int)blockIdx.x) : (int)blockIdx.x;
    const int q0 = qt * 64;

    float oacc[16][4];
    float mrow[2], lrow_s[2];
#pragma unroll
    for (int h = 0; h < 2; h++) { mrow[h] = -3.0e38f; lrow_s[h] = 0.f; }
#pragma unroll
    for (int nt = 0; nt < 16; nt++)
#pragma unroll
      for (int j = 0; j < 4; j++) oacc[nt][j] = 0.f;

    issueQ(q0);
    issueKV(0, 0);
    cp_commit();

    for (int kt = 0; kt <= qt; kt++) {
      if (kt < qt) {
        issueKV(kt + 1, (kt + 1) & 1);
        cp_commit();
        cp_wait1();
      } else {
        cp_wait0();
      }
      __syncthreads();   // A: buffers ready

      const uint32_t buf = sb + (kt & 1) * KVBUF;
      const int k0 = kt * 64;

      // ---- S = Q K^T for this warp's map: 16 rows x 64 keys ----
      float sacc[8][4];
#pragma unroll
      for (int nt = 0; nt < 8; nt++)
#pragma unroll
        for (int j = 0; j < 4; j++) sacc[nt][j] = 0.f;

      {
        const uint32_t Qh = sb + AOFF_Q + m * 8192;
        const uint32_t Ql = sb + AOFF_Q + 16384 + m * 8192;
        const uint32_t Kh = buf + m * 8192;
        const uint32_t Kl = buf + 16384 + m * 8192;
#pragma unroll
        for (int ks = 0; ks < 4; ks++) {
          const int colb = ks * 32 + selc;
          uint32_t aoff = sw128((uint32_t)((wm + selm + lrow) * 128 + colb));
          uint32_t qh[4], ql[4];
          ldsm4(qh, Qh + aoff);
          ldsm4(ql, Ql + aoff);
          uint32_t bh[8][2], bl[8][2];
#pragma unroll
          for (int np = 0; np < 4; np++) {
            uint32_t boff = sw128((uint32_t)((np * 16 + selm + lrow) * 128 + colb));
            uint32_t t4[4];
            ldsm4(t4, Kh + boff);
            bh[2 * np][0] = t4[0]; bh[2 * np][1] = t4[2];
            bh[2 * np + 1][0] = t4[1]; bh[2 * np + 1][1] = t4[3];
            ldsm4(t4, Kl + boff);
            bl[2 * np][0] = t4[0]; bl[2 * np][1] = t4[2];
            bl[2 * np + 1][0] = t4[1]; bl[2 * np + 1][1] = t4[3];
          }
#pragma unroll
          for (int nt = 0; nt < 8; nt++) {
            mma16816(sacc[nt], qh, bh[nt][0], bh[nt][1]);
            mma16816(sacc[nt], ql, bh[nt][0], bh[nt][1]);
            mma16816(sacc[nt], qh, bl[nt][0], bl[nt][1]);
          }
        }
      }

      // ---- warp-local softmax (QSCALE pre-folded into Q) ----
      const bool diag = (kt == qt);
      float mx[2] = {-3.0e38f, -3.0e38f};
#pragma unroll
      for (int nt = 0; nt < 8; nt++)
#pragma unroll
        for (int h = 0; h < 2; h++)
#pragma unroll
          for (int j = 0; j < 2; j++) {
            float v = sacc[nt][h * 2 + j];
            if (diag && (k0 + nt * 8 + cq + j) > (q0 + wm + r + h * 8)) v = -3.0e38f;
            sacc[nt][h * 2 + j] = v;
            mx[h] = fmaxf(mx[h], v);
          }
#pragma unroll
      for (int h = 0; h < 2; h++) {
        mx[h] = fmaxf(mx[h], __shfl_xor_sync(0xffffffffu, mx[h], 1));
        mx[h] = fmaxf(mx[h], __shfl_xor_sync(0xffffffffu, mx[h], 2));
      }

      float alpha[2], lsum[2] = {0.f, 0.f};
#pragma unroll
      for (int h = 0; h < 2; h++) {
        float mn = fmaxf(mrow[h], mx[h]);
        alpha[h] = fast_exp2(mrow[h] - mn);
        mrow[h] = mn;
      }

      uint32_t pfh[4][4], pfl[4][4];
#pragma unroll
      for (int nt = 0; nt < 8; nt++)
#pragma unroll
        for (int h = 0; h < 2; h++) {
          float p0 = fast_exp2(sacc[nt][h * 2 + 0] - mrow[h]);
          float p1 = fast_exp2(sacc[nt][h * 2 + 1] - mrow[h]);
          lsum[h] += p0 + p1;
          sacc[nt][h * 2 + 0] = p0;
          sacc[nt][h * 2 + 1] = p1;
        }
#pragma unroll
      for (int ks = 0; ks < 4; ks++) {
        hilo_t(sacc[2 * ks][0], sacc[2 * ks][1], pfh[ks][0], pfl[ks][0]);
        hilo_t(sacc[2 * ks][2], sacc[2 * ks][3], pfh[ks][1], pfl[ks][1]);
        hilo_t(sacc[2 * ks + 1][0], sacc[2 * ks + 1][1], pfh[ks][2], pfl[ks][2]);
        hilo_t(sacc[2 * ks + 1][2], sacc[2 * ks + 1][3], pfh[ks][3], pfl[ks][3]);
      }
#pragma unroll
      for (int h = 0; h < 2; h++) {
        lsum[h] += __shfl_xor_sync(0xffffffffu, lsum[h], 1);
        lsum[h] += __shfl_xor_sync(0xffffffffu, lsum[h], 2);
        lrow_s[h] = lrow_s[h] * alpha[h] + lsum[h];
      }
#pragma unroll
      for (int nt = 0; nt < 16; nt++) {
        oacc[nt][0] *= alpha[0];
        oacc[nt][1] *= alpha[0];
        oacc[nt][2] *= alpha[1];
        oacc[nt][3] *= alpha[1];
      }

      // ---- O += P V ----
#pragma unroll
      for (int ks = 0; ks < 4; ks++) {
        const int vrow = ks * 16 + selm + lrow;
#pragma unroll
        for (int np = 0; np < 8; np++) {
          const int part = np >> 2;
          const uint32_t boff = (uint32_t)part * 8192 +
              sw128((uint32_t)(vrow * 128 + (np & 3) * 32 + selc));
          uint32_t vh4[4], vl4[4];
          ldsm4t(vh4, buf + 32768 + boff);
          ldsm4t(vl4, buf + 49152 + boff);
#pragma unroll
          for (int e = 0; e < 2; e++) {
            float* d = oacc[2 * np + e];
            mma16816(d, pfh[ks], vh4[2 * e], vh4[2 * e + 1]);
            mma16816(d, pfl[ks], vh4[2 * e], vh4[2 * e + 1]);
            mma16816(d, pfh[ks], vl4[2 * e], vl4[2 * e + 1]);
          }
        }
      }
      __syncthreads();   // D: protect KV buffer reuse
    }

    // ---- epilogue: cross-map combine + output LN ----
    if (m == 1) {
      float inv2[2];
#pragma unroll
      for (int h = 0; h < 2; h++) inv2[h] = lam / lrow_s[h];
#pragma unroll
      for (int nt = 0; nt < 16; nt++)
#pragma unroll
        for (int h = 0; h < 2; h++) {
          int rr = wm + r + h * 8;
          SCR[rr * 132 + nt * 8 + cq]     = oacc[nt][h * 2 + 0] * inv2[h];
          SCR[rr * 132 + nt * 8 + cq + 1] = oacc[nt][h * 2 + 1] * inv2[h];
        }
    }
    __syncthreads();
    if (m == 0) {
      float inv1[2];
#pragma unroll
      for (int h = 0; h < 2; h++) inv1[h] = 1.0f / lrow_s[h];
      float att[16][4];
      float rs[2] = {0.f, 0.f};
#pragma unroll
      for (int nt = 0; nt < 16; nt++)
#pragma unroll
        for (int h = 0; h < 2; h++) {
          int rr = wm + r + h * 8;
          float a0 = oacc[nt][h * 2 + 0] * inv1[h] - SCR[rr * 132 + nt * 8 + cq];
          float a1 = oacc[nt][h * 2 + 1] * inv1[h] - SCR[rr * 132 + nt * 8 + cq + 1];
          att[nt][h * 2 + 0] = a0;
          att[nt][h * 2 + 1] = a1;
          rs[h] += a0 + a1;
        }
#pragma unroll
      for (int h = 0; h < 2; h++) {
        rs[h] += __shfl_xor_sync(0xffffffffu, rs[h], 1);
        rs[h] += __shfl_xor_sync(0xffffffffu, rs[h], 2);
      }
      float mean_[2];
#pragma unroll
      for (int h = 0; h < 2; h++) mean_[h] = rs[h] * (1.0f / 128.0f);

      float vs[2] = {0.f, 0.f};
#pragma unroll
      for (int nt = 0; nt < 16; nt++)
#pragma unroll
        for (int h = 0; h < 2; h++)
#pragma unroll
          for (int j = 0; j < 2; j++) {
            float a = att[nt][h * 2 + j] - mean_[h];
            vs[h] += a * a;
          }
#pragma unroll
      for (int h = 0; h < 2; h++) {
        vs[h] += __shfl_xor_sync(0xffffffffu, vs[h], 1);
        vs[h] += __shfl_xor_sync(0xffffffffu, vs[h], 2);
      }
      float rstd_[2];
#pragma unroll
      for (int h = 0; h < 2; h++)
        rstd_[h] = rsqrtf(vs[h] * (1.0f / 128.0f) + 1e-5f);

#pragma unroll
      for (int nt = 0; nt < 16; nt++) {
        int c = nt * 8 + cq;
        float2 g2 = *(const float2*)&gam[c];
        float2 b2 = *(const float2*)&bet[c];
#pragma unroll
        for (int h = 0; h < 2; h++) {
          float o0 = (att[nt][h * 2 + 0] - mean_[h]) * rstd_[h] * g2.x + b2.x;
          float o1 = (att[nt][h * 2 + 1] - mean_[h]) * rstd_[h] * g2.y + b2.y;
          size_t off = (size_t)(rowbase + q0 + wm + r + h * 8) * 128 + c;
          *(float2*)&out[off] = make_float2(o0, o1);
        }
      }
    }
    __syncthreads();   // protect SCR + smem before next half
  }
}

// ---------------- launch ----------------
extern "C" void kernel_launch(void* const* d_in, const int* in_sizes, int n_in,
                              void* d_out, int out_size) {
  const float* x     = (const float*)d_in[0];
  const float* Wq    = (const float*)d_in[1];
  const float* Wk    = (const float*)d_in[2];
  const float* Wv    = (const float*)d_in[3];
  const float* Wq_ss = (const float*)d_in[4];
  const float* Wk_ss = (const float*)d_in[5];
  const float* Wv_ss = (const float*)d_in[6];
  const float* Wq_se = (const float*)d_in[7];
  const float* Wk_se = (const float*)d_in[8];
  const float* Wv_se = (const float*)d_in[9];
  const float* g_in  = (const float*)d_in[10];
  const float* b_in  = (const float*)d_in[11];
  const float* g_ss  = (const float*)d_in[12];
  const float* b_ss  = (const float*)d_in[13];
  const float* g_se  = (const float*)d_in[14];
  const float* b_se  = (const float*)d_in[15];
  const float* g_out = (const float*)d_in[16];
  const float* b_out = (const float*)d_in[17];
  const float* lq1   = (const float*)d_in[18];
  const float* lq2   = (const float*)d_in[19];
  const float* lk1   = (const float*)d_in[20];
  const float* lk2   = (const float*)d_in[21];

  static bool attr_set = false;
  if (!attr_set) {
    cudaFuncSetAttribute(proj_mma_kernel, cudaFuncAttributeMaxDynamicSharedMemorySize,
                         PROJ_SMEM);
    cudaFuncSetAttribute(attn_mma_kernel, cudaFuncAttributeMaxDynamicSharedMemorySize,
                         ATTN_SMEM);
    attr_set = true;
  }

  WPrepParams wp;
  wp.W[0] = Wq_ss; wp.W[1] = Wq; wp.W[2] = Wq_se;
  wp.W[3] = Wk_ss; wp.W[4] = Wk; wp.W[5] = Wk_se;
  wp.W[6] = Wv_ss; wp.W[7] = Wv; wp.W[8] = Wv_se;
  wp.lq1 = lq1; wp.lq2 = lq2; wp.lk1 = lk1; wp.lk2 = lk2;
  wprep_kernel<<<dim3(32, 4, 9), dim3(32, 32)>>>(wp);

  NormParams np;
  np.x = x;
  np.g[0] = g_ss; np.g[1] = g_in; np.g[2] = g_se;
  np.b[0] = b_ss; np.b[1] = b_in; np.b[2] = b_se;
  norm_split_kernel<<<NROW / 8, dim3(32, 8)>>>(np);

  proj_mma_kernel<<<dim3(144, 3, 2), 256, PROJ_SMEM>>>();

  attn_mma_kernel<<<dim3(18, 8), 256, ATTN_SMEM>>>(g_out, b_out, (float*)d_out);
}